// round 2
// baseline (speedup 1.0000x reference)
#include <cuda_runtime.h>
#include <cstddef>

// ---------------------------------------------------------------------------
// GraphConvolution: algebraically simplified to
//   e        = H_e @ p^T                         [E]        E=8192, IN_E=128
//   M1       = (T * e) @ T^T                     [N,N]      N=4096, K=E=8192
//   Bcomb    = 0.5*(M1'+1) .* adj_v   (M1' has diag forced to 1)
//   Y        = Bcomb @ H_v                       [N,512]
//   ret      = Y @ W + bias                      [N,512]
//   out      = concat(ret, H_e)
// adj_e is unused by the reference.
// ---------------------------------------------------------------------------

#define N_NODES 4096
#define E_EDGES 8192
#define IN_V    512
#define OUT_V   512
#define IN_E    128

// Scratch (static device globals: allocation-free per harness rules)
__device__ float g_escale[E_EDGES];                      // 32 KB
__device__ float g_mult1[(size_t)N_NODES * N_NODES];     // 64 MB
__device__ float g_Y[(size_t)N_NODES * IN_V];            // 8 MB

// ---------------------------------------------------------------------------
// Kernel 1: e[r] = dot(H_e[r, :], p[:])   (IN_E = 128)  one warp per row
// ---------------------------------------------------------------------------
__global__ void escale_kernel(const float* __restrict__ He,
                              const float* __restrict__ p) {
    int warp = threadIdx.x >> 5;
    int lane = threadIdx.x & 31;
    int row  = blockIdx.x * 8 + warp;
    if (row >= E_EDGES) return;
    const float* hr = He + (size_t)row * IN_E;
    float s = 0.f;
#pragma unroll
    for (int i = 0; i < IN_E; i += 32)
        s += hr[i + lane] * p[i + lane];
#pragma unroll
    for (int off = 16; off > 0; off >>= 1)
        s += __shfl_down_sync(0xffffffffu, s, off);
    if (lane == 0) g_escale[row] = s;
}

// ---------------------------------------------------------------------------
// Kernel 2: g_mult1 = (T * diag(e)) @ T^T    M=N=4096, K=8192
// Classic 128x128x16 block tile, 8x8 per thread, 256 threads.
// ---------------------------------------------------------------------------
__global__ __launch_bounds__(256, 1)
void gemm1_kernel(const float* __restrict__ T) {
    __shared__ float As[16][128];
    __shared__ float Bs[16][128];

    const int tid = threadIdx.x;
    const int ty  = tid >> 4;   // 0..15
    const int tx  = tid & 15;   // 0..15
    const int rowbase = blockIdx.y * 128;
    const int colbase = blockIdx.x * 128;

    float acc[8][8];
#pragma unroll
    for (int m = 0; m < 8; m++)
#pragma unroll
        for (int n = 0; n < 8; n++) acc[m][n] = 0.f;

    for (int k0 = 0; k0 < E_EDGES; k0 += 16) {
        // Load 128x16 A tile (scaled by e) and 128x16 B tile, store transposed.
#pragma unroll
        for (int l = 0; l < 2; l++) {
            int t  = tid + l * 256;      // 0..511 float4 slots
            int r  = t >> 2;             // 0..127
            int c4 = (t & 3) * 4;        // 0,4,8,12
            float4 ev = *(const float4*)&g_escale[k0 + c4];
            float4 v  = *(const float4*)&T[(size_t)(rowbase + r) * E_EDGES + k0 + c4];
            As[c4 + 0][r] = v.x * ev.x;
            As[c4 + 1][r] = v.y * ev.y;
            As[c4 + 2][r] = v.z * ev.z;
            As[c4 + 3][r] = v.w * ev.w;
            float4 w = *(const float4*)&T[(size_t)(colbase + r) * E_EDGES + k0 + c4];
            Bs[c4 + 0][r] = w.x;
            Bs[c4 + 1][r] = w.y;
            Bs[c4 + 2][r] = w.z;
            Bs[c4 + 3][r] = w.w;
        }
        __syncthreads();

#pragma unroll
        for (int k = 0; k < 16; k++) {
            float a[8], b[8];
            *(float4*)&a[0] = *(float4*)&As[k][ty * 8];
            *(float4*)&a[4] = *(float4*)&As[k][ty * 8 + 4];
            *(float4*)&b[0] = *(float4*)&Bs[k][tx * 8];
            *(float4*)&b[4] = *(float4*)&Bs[k][tx * 8 + 4];
#pragma unroll
            for (int m = 0; m < 8; m++)
#pragma unroll
                for (int n = 0; n < 8; n++)
                    acc[m][n] = fmaf(a[m], b[n], acc[m][n]);
        }
        __syncthreads();
    }

#pragma unroll
    for (int m = 0; m < 8; m++) {
        int gi = rowbase + ty * 8 + m;
        float* crow = g_mult1 + (size_t)gi * N_NODES + colbase + tx * 8;
#pragma unroll
        for (int n = 0; n < 8; n += 4) {
            float4 v = make_float4(acc[m][n], acc[m][n + 1], acc[m][n + 2], acc[m][n + 3]);
            *(float4*)&crow[n] = v;
        }
    }
}

// ---------------------------------------------------------------------------
// Kernel 3: Y = Bcomb @ H_v.  Bcomb computed on the fly from mult1 & adj_v:
//   Bcomb[i][j] = 0.5*((i==j ? 1 : mult1[i][j]) + 1) * adj_v[i][j]
// M=4096, N=512, K=4096. 128x128x16 tiles.
// ---------------------------------------------------------------------------
__global__ __launch_bounds__(256, 1)
void gemm2_kernel(const float* __restrict__ adj_v,
                  const float* __restrict__ Hv) {
    __shared__ float As[16][128];
    __shared__ float Bs[16][128];

    const int tid = threadIdx.x;
    const int ty  = tid >> 4;
    const int tx  = tid & 15;
    const int rowbase = blockIdx.y * 128;
    const int colbase = blockIdx.x * 128;

    float acc[8][8];
#pragma unroll
    for (int m = 0; m < 8; m++)
#pragma unroll
        for (int n = 0; n < 8; n++) acc[m][n] = 0.f;

    for (int k0 = 0; k0 < N_NODES; k0 += 16) {
        // A tile: rows = i (M dim), cols = j (K dim) with fused elementwise
#pragma unroll
        for (int l = 0; l < 2; l++) {
            int t  = tid + l * 256;
            int r  = t >> 2;
            int c4 = (t & 3) * 4;
            int gi = rowbase + r;
            int gj = k0 + c4;
            float4 mv = *(const float4*)&g_mult1[(size_t)gi * N_NODES + gj];
            float4 av = *(const float4*)&adj_v[(size_t)gi * N_NODES + gj];
            float m0 = (gi == gj + 0) ? 1.f : mv.x;
            float m1 = (gi == gj + 1) ? 1.f : mv.y;
            float m2 = (gi == gj + 2) ? 1.f : mv.z;
            float m3 = (gi == gj + 3) ? 1.f : mv.w;
            As[c4 + 0][r] = 0.5f * (m0 + 1.f) * av.x;
            As[c4 + 1][r] = 0.5f * (m1 + 1.f) * av.y;
            As[c4 + 2][r] = 0.5f * (m2 + 1.f) * av.z;
            As[c4 + 3][r] = 0.5f * (m3 + 1.f) * av.w;
        }
        // B tile: 16 rows (K) x 128 cols (N) from H_v
#pragma unroll
        for (int l = 0; l < 2; l++) {
            int t  = tid + l * 256;
            int r  = t >> 5;            // 0..15
            int c4 = (t & 31) * 4;      // 0..124
            *(float4*)&Bs[r][c4] =
                *(const float4*)&Hv[(size_t)(k0 + r) * IN_V + colbase + c4];
        }
        __syncthreads();

#pragma unroll
        for (int k = 0; k < 16; k++) {
            float a[8], b[8];
            *(float4*)&a[0] = *(float4*)&As[k][ty * 8];
            *(float4*)&a[4] = *(float4*)&As[k][ty * 8 + 4];
            *(float4*)&b[0] = *(float4*)&Bs[k][tx * 8];
            *(float4*)&b[4] = *(float4*)&Bs[k][tx * 8 + 4];
#pragma unroll
            for (int m = 0; m < 8; m++)
#pragma unroll
                for (int n = 0; n < 8; n++)
                    acc[m][n] = fmaf(a[m], b[n], acc[m][n]);
        }
        __syncthreads();
    }

#pragma unroll
    for (int m = 0; m < 8; m++) {
        int gi = rowbase + ty * 8 + m;
        float* yrow = g_Y + (size_t)gi * IN_V + colbase + tx * 8;
#pragma unroll
        for (int n = 0; n < 8; n += 4)
            *(float4*)&yrow[n] = make_float4(acc[m][n], acc[m][n + 1],
                                             acc[m][n + 2], acc[m][n + 3]);
    }
}

// ---------------------------------------------------------------------------
// Kernel 4: ret = Y @ W + bias.  M=4096, N=512, K=512.
// ---------------------------------------------------------------------------
__global__ __launch_bounds__(256, 1)
void gemm3_kernel(const float* __restrict__ W,
                  const float* __restrict__ bias,
                  float* __restrict__ out) {
    __shared__ float As[16][128];
    __shared__ float Bs[16][128];

    const int tid = threadIdx.x;
    const int ty  = tid >> 4;
    const int tx  = tid & 15;
    const int rowbase = blockIdx.y * 128;
    const int colbase = blockIdx.x * 128;

    float acc[8][8];
#pragma unroll
    for (int m = 0; m < 8; m++)
#pragma unroll
        for (int n = 0; n < 8; n++) acc[m][n] = 0.f;

    for (int k0 = 0; k0 < IN_V; k0 += 16) {
#pragma unroll
        for (int l = 0; l < 2; l++) {
            int t  = tid + l * 256;
            int r  = t >> 2;
            int c4 = (t & 3) * 4;
            float4 v = *(const float4*)&g_Y[(size_t)(rowbase + r) * IN_V + k0 + c4];
            As[c4 + 0][r] = v.x;
            As[c4 + 1][r] = v.y;
            As[c4 + 2][r] = v.z;
            As[c4 + 3][r] = v.w;
        }
#pragma unroll
        for (int l = 0; l < 2; l++) {
            int t  = tid + l * 256;
            int r  = t >> 5;
            int c4 = (t & 31) * 4;
            *(float4*)&Bs[r][c4] =
                *(const float4*)&W[(size_t)(k0 + r) * OUT_V + colbase + c4];
        }
        __syncthreads();

#pragma unroll
        for (int k = 0; k < 16; k++) {
            float a[8], b[8];
            *(float4*)&a[0] = *(float4*)&As[k][ty * 8];
            *(float4*)&a[4] = *(float4*)&As[k][ty * 8 + 4];
            *(float4*)&b[0] = *(float4*)&Bs[k][tx * 8];
            *(float4*)&b[4] = *(float4*)&Bs[k][tx * 8 + 4];
#pragma unroll
            for (int m = 0; m < 8; m++)
#pragma unroll
                for (int n = 0; n < 8; n++)
                    acc[m][n] = fmaf(a[m], b[n], acc[m][n]);
        }
        __syncthreads();
    }

#pragma unroll
    for (int m = 0; m < 8; m++) {
        int gi = rowbase + ty * 8 + m;
        int gj = colbase + tx * 8;
        float* orow = out + (size_t)gi * OUT_V + gj;
#pragma unroll
        for (int n = 0; n < 8; n += 4) {
            float4 bv = *(const float4*)&bias[gj + n];
            *(float4*)&orow[n] = make_float4(acc[m][n] + bv.x, acc[m][n + 1] + bv.y,
                                             acc[m][n + 2] + bv.z, acc[m][n + 3] + bv.w);
        }
    }
}

// ---------------------------------------------------------------------------
extern "C" void kernel_launch(void* const* d_in, const int* in_sizes, int n_in,
                              void* d_out, int out_size) {
    const float* H_v   = (const float*)d_in[0];
    const float* H_e   = (const float*)d_in[1];
    // d_in[2] = adj_e : UNUSED by the reference
    const float* adj_v = (const float*)d_in[3];
    const float* T     = (const float*)d_in[4];
    const float* W     = (const float*)d_in[5];
    const float* p     = (const float*)d_in[6];
    const float* bias  = (const float*)d_in[7];
    float* out = (float*)d_out;

    // 1. e = H_e @ p^T
    escale_kernel<<<E_EDGES / 8, 256>>>(H_e, p);

    // 2. mult1 = (T * e) @ T^T
    {
        dim3 grid(N_NODES / 128, N_NODES / 128);
        gemm1_kernel<<<grid, 256>>>(T);
    }

    // 3. Y = (0.5*(M1'+1) .* adj_v) @ H_v
    {
        dim3 grid(IN_V / 128, N_NODES / 128);
        gemm2_kernel<<<grid, 256>>>(adj_v, H_v);
    }

    // 4. ret = Y @ W + bias  -> front of d_out
    {
        dim3 grid(OUT_V / 128, N_NODES / 128);
        gemm3_kernel<<<grid, 256>>>(W, bias, out);
    }

    // 5. second output: H_e passthrough -> tail of d_out
    int he_elems = in_sizes[1];
    cudaMemcpyAsync(out + ((size_t)out_size - he_elems), H_e,
                    (size_t)he_elems * sizeof(float),
                    cudaMemcpyDeviceToDevice, 0);
}

// round 4
// speedup vs baseline: 2.9346x; 2.9346x over previous
#include <cuda_runtime.h>
#include <cuda_bf16.h>
#include <cstdint>
#include <cstddef>

// ---------------------------------------------------------------------------
// GraphConvolution, algebraically simplified:
//   e     = H_e @ p^T                      [E]
//   M1    = (T*diag(e)) @ T^T              [N,N]   <-- mma.sync bf16-split GEMM
//   Y     = (0.5*(M1'+1) .* adj_v) @ H_v   [N,512] (M1' diag forced to 1)
//   ret   = Y @ W + bias                   [N,512]
//   out   = concat(ret, H_e)
// NOTE: harness compiles PTX for base sm_103 (no 'a' features) -> tcgen05 is
// unavailable. Use sm_80-class mma.sync HMMA path instead.
// ---------------------------------------------------------------------------

#define N_NODES 4096
#define E_EDGES 8192
#define IN_V    512
#define OUT_V   512
#define IN_E    128
#define KC      64                 // bf16 K elements per chunk
#define NCHUNK  (E_EDGES / KC)

// Static device scratch (allocation-free per harness rules)
__device__ float g_escale[E_EDGES];
__device__ float g_mult1[(size_t)N_NODES * N_NODES];        // 64 MB
__device__ float g_Y[(size_t)N_NODES * IN_V];               // 8 MB
__device__ __nv_bfloat16 g_Ghi[(size_t)N_NODES * E_EDGES];  // 64 MB each
__device__ __nv_bfloat16 g_Glo[(size_t)N_NODES * E_EDGES];
__device__ __nv_bfloat16 g_Thi[(size_t)N_NODES * E_EDGES];
__device__ __nv_bfloat16 g_Tlo[(size_t)N_NODES * E_EDGES];

// ------------------------------ helpers ------------------------------------
__device__ __forceinline__ uint32_t smem_u32(const void* p) {
    uint32_t a;
    asm("{ .reg .u64 t; cvta.to.shared.u64 t, %1; cvt.u32.u64 %0, t; }"
        : "=r"(a) : "l"(p));
    return a;
}
__device__ __forceinline__ uint32_t swz(uint32_t x) { return x ^ ((x >> 3) & 0x70u); }

__device__ __forceinline__ void ldsm_x4(uint32_t& a0, uint32_t& a1,
                                        uint32_t& a2, uint32_t& a3, uint32_t addr) {
    asm volatile("ldmatrix.sync.aligned.m8n8.x4.shared.b16 {%0,%1,%2,%3}, [%4];"
                 : "=r"(a0), "=r"(a1), "=r"(a2), "=r"(a3) : "r"(addr));
}
__device__ __forceinline__ void ldsm_x2(uint32_t& b0, uint32_t& b1, uint32_t addr) {
    asm volatile("ldmatrix.sync.aligned.m8n8.x2.shared.b16 {%0,%1}, [%2];"
                 : "=r"(b0), "=r"(b1) : "r"(addr));
}
__device__ __forceinline__ void mma_bf16(float* d, const uint32_t* a, const uint32_t* b) {
    asm volatile(
        "mma.sync.aligned.m16n8k16.row.col.f32.bf16.bf16.f32 "
        "{%0,%1,%2,%3}, {%4,%5,%6,%7}, {%8,%9}, {%0,%1,%2,%3};"
        : "+f"(d[0]), "+f"(d[1]), "+f"(d[2]), "+f"(d[3])
        : "r"(a[0]), "r"(a[1]), "r"(a[2]), "r"(a[3]), "r"(b[0]), "r"(b[1]));
}

// ---------------------------------------------------------------------------
// Kernel 1: e[r] = dot(H_e[r,:], p)
// ---------------------------------------------------------------------------
__global__ void escale_kernel(const float* __restrict__ He,
                              const float* __restrict__ p) {
    int warp = threadIdx.x >> 5;
    int lane = threadIdx.x & 31;
    int row  = blockIdx.x * 8 + warp;
    if (row >= E_EDGES) return;
    const float* hr = He + (size_t)row * IN_E;
    float s = 0.f;
#pragma unroll
    for (int i = 0; i < IN_E; i += 32)
        s += hr[i + lane] * p[i + lane];
#pragma unroll
    for (int off = 16; off > 0; off >>= 1)
        s += __shfl_down_sync(0xffffffffu, s, off);
    if (lane == 0) g_escale[row] = s;
}

// ---------------------------------------------------------------------------
// Kernel 1b: split T and G=T*diag(e) into bf16 hi/lo pairs
// ---------------------------------------------------------------------------
__global__ __launch_bounds__(256)
void convert_kernel(const float* __restrict__ T) {
    unsigned g   = blockIdx.x * 256u + threadIdx.x;   // float4 index
    unsigned row = g >> 11;                           // 2048 float4 per row
    unsigned k4  = (g & 2047u) * 4u;
    size_t base = (size_t)row * E_EDGES + k4;
    float4 t = *(const float4*)(T + base);
    float4 e = *(const float4*)(g_escale + k4);
    float gv[4] = {t.x * e.x, t.y * e.y, t.z * e.z, t.w * e.w};
    float tv[4] = {t.x, t.y, t.z, t.w};
    unsigned short ghi[4], glo[4], thi[4], tlo[4];
#pragma unroll
    for (int i = 0; i < 4; i++) {
        __nv_bfloat16 h = __float2bfloat16(gv[i]);
        __nv_bfloat16 l = __float2bfloat16(gv[i] - __bfloat162float(h));
        ghi[i] = __bfloat16_as_ushort(h);
        glo[i] = __bfloat16_as_ushort(l);
        h = __float2bfloat16(tv[i]);
        l = __float2bfloat16(tv[i] - __bfloat162float(h));
        thi[i] = __bfloat16_as_ushort(h);
        tlo[i] = __bfloat16_as_ushort(l);
    }
#define PACK2(a) make_uint2((unsigned)(a)[0] | ((unsigned)(a)[1] << 16), \
                            (unsigned)(a)[2] | ((unsigned)(a)[3] << 16))
    *(uint2*)(g_Ghi + base) = PACK2(ghi);
    *(uint2*)(g_Glo + base) = PACK2(glo);
    *(uint2*)(g_Thi + base) = PACK2(thi);
    *(uint2*)(g_Tlo + base) = PACK2(tlo);
#undef PACK2
}

// ---------------------------------------------------------------------------
// Kernel 2: g_mult1 = G @ T^T, bf16 split (Ghi*Thi + Ghi*Tlo + Glo*Thi).
// CTA: 128x128 tile, 8 warps (2x4), warp tile 64x32. mma.sync m16n8k16.
// cp.async double-buffered K chunks of 64 bf16 (4 arrays x 16KB per stage).
// ---------------------------------------------------------------------------
#define STAGE_BYTES 65536
#define GEMM1_SMEM  (2 * STAGE_BYTES)

__global__ __launch_bounds__(256, 1)
void gemm1_mma() {
    extern __shared__ char smem[];
    uint32_t sb = smem_u32(smem);
    const int tid  = threadIdx.x;
    const int wid  = tid >> 5;
    const int lane = tid & 31;
    const int wr   = wid >> 2;        // warp row 0..1  (64 rows each)
    const int wc   = wid & 3;         // warp col 0..3  (32 cols each)

    // Rasterize into 8-column panels for L2 reuse.
    unsigned linear  = blockIdx.y * gridDim.x + blockIdx.x;
    unsigned panel   = linear >> 8;
    unsigned rem     = linear & 255u;
    unsigned rowtile = rem >> 3;
    unsigned coltile = (panel << 3) | (rem & 7u);
    const unsigned rowbase = rowtile * 128u;
    const unsigned colbase = coltile * 128u;

    float acc[4][4][4];
#pragma unroll
    for (int m = 0; m < 4; m++)
#pragma unroll
        for (int n = 0; n < 4; n++)
#pragma unroll
            for (int i = 0; i < 4; i++) acc[m][n][i] = 0.f;

    auto load_chunk = [&](int c, int s) {
        uint32_t sbase = sb + (uint32_t)s * STAGE_BYTES;
        unsigned kbase = (unsigned)c * KC;
#pragma unroll
        for (int l = 0; l < 16; l++) {
            const int arr = l >> 2;                 // 0:Ahi 1:Alo 2:Bhi 3:Blo
            const int ci  = (l & 3) * 256 + tid;    // 0..1023 slot in tile
            const int r   = ci >> 3;                // row 0..127
            const int q   = ci & 7;                 // 16B chunk 0..7
            const __nv_bfloat16* src;
            unsigned grow;
            if (arr == 0)      { src = g_Ghi; grow = rowbase + r; }
            else if (arr == 1) { src = g_Glo; grow = rowbase + r; }
            else if (arr == 2) { src = g_Thi; grow = colbase + r; }
            else               { src = g_Tlo; grow = colbase + r; }
            const void* gp = (const void*)(src + (size_t)grow * E_EDGES + kbase + q * 8);
            uint32_t dp = sbase + (uint32_t)arr * 16384u + swz((uint32_t)(r * 128 + q * 16));
            asm volatile("cp.async.cg.shared.global [%0], [%1], 16;" :: "r"(dp), "l"(gp));
        }
    };

    load_chunk(0, 0);
    asm volatile("cp.async.commit_group;" ::: "memory");

    for (int c = 0; c < NCHUNK; c++) {
        int s = c & 1;
        if (c + 1 < NCHUNK) load_chunk(c + 1, s ^ 1);
        asm volatile("cp.async.commit_group;" ::: "memory");
        asm volatile("cp.async.wait_group 1;" ::: "memory");
        __syncthreads();

        uint32_t stage = sb + (uint32_t)s * STAGE_BYTES;
        uint32_t aHiB = stage;                 // Ahi
        uint32_t aLoB = stage + 16384u;        // Alo
        uint32_t bHiB = stage + 32768u;        // Bhi
        uint32_t bLoB = stage + 49152u;        // Blo

        // ldmatrix lane address components
        const int la_row = lane & 15;          // A: matrix row
        const int la_kh  = lane >> 4;          // A: k-half (0/1) -> +16B
        const int lb     = lane & 15;
        const int lb_row = lb & 7;             // B: n row within tile
        const int lb_kh  = (lb >> 3) & 1;      // B: k-half

#pragma unroll
        for (int ks = 0; ks < 4; ks++) {       // k16 steps within chunk
            uint32_t ahi[4][4], alo[4][4], bhi[4][2], blo[4][2];
#pragma unroll
            for (int mt = 0; mt < 4; mt++) {
                uint32_t off = swz((uint32_t)((wr * 64 + mt * 16 + la_row) * 128
                                              + ks * 32 + la_kh * 16));
                ldsm_x4(ahi[mt][0], ahi[mt][1], ahi[mt][2], ahi[mt][3], aHiB + off);
                ldsm_x4(alo[mt][0], alo[mt][1], alo[mt][2], alo[mt][3], aLoB + off);
            }
#pragma unroll
            for (int nt = 0; nt < 4; nt++) {
                uint32_t off = swz((uint32_t)((wc * 32 + nt * 8 + lb_row) * 128
                                              + ks * 32 + lb_kh * 16));
                ldsm_x2(bhi[nt][0], bhi[nt][1], bHiB + off);
                ldsm_x2(blo[nt][0], blo[nt][1], bLoB + off);
            }
#pragma unroll
            for (int mt = 0; mt < 4; mt++)
#pragma unroll
                for (int nt = 0; nt < 4; nt++) {
                    mma_bf16(acc[mt][nt], ahi[mt], bhi[nt]);
                    mma_bf16(acc[mt][nt], ahi[mt], blo[nt]);
                    mma_bf16(acc[mt][nt], alo[mt], bhi[nt]);
                }
        }
        __syncthreads();
    }

    // Epilogue: d0,d1 -> row lane/4, cols 2*(lane%4)+{0,1}; d2,d3 -> row+8.
#pragma unroll
    for (int mt = 0; mt < 4; mt++) {
        unsigned row0 = rowbase + wr * 64 + mt * 16 + (lane >> 2);
#pragma unroll
        for (int nt = 0; nt < 4; nt++) {
            unsigned col = colbase + wc * 32 + nt * 8 + 2 * (lane & 3);
            *(float2*)&g_mult1[(size_t)row0 * N_NODES + col] =
                make_float2(acc[mt][nt][0], acc[mt][nt][1]);
            *(float2*)&g_mult1[(size_t)(row0 + 8) * N_NODES + col] =
                make_float2(acc[mt][nt][2], acc[mt][nt][3]);
        }
    }
}

// ---------------------------------------------------------------------------
// Kernel 3: Y = (0.5*(M1'+1) .* adj_v) @ H_v   (fp32 SIMT, K=4096)
// ---------------------------------------------------------------------------
__global__ __launch_bounds__(256, 1)
void gemm2_kernel(const float* __restrict__ adj_v,
                  const float* __restrict__ Hv) {
    __shared__ float As[16][128];
    __shared__ float Bs[16][128];

    const int tid = threadIdx.x;
    const int ty  = tid >> 4;
    const int tx  = tid & 15;
    const int rowbase = blockIdx.y * 128;
    const int colbase = blockIdx.x * 128;

    float acc[8][8];
#pragma unroll
    for (int m = 0; m < 8; m++)
#pragma unroll
        for (int n = 0; n < 8; n++) acc[m][n] = 0.f;

    for (int k0 = 0; k0 < N_NODES; k0 += 16) {
#pragma unroll
        for (int l = 0; l < 2; l++) {
            int t  = tid + l * 256;
            int r  = t >> 2;
            int c4 = (t & 3) * 4;
            int gi = rowbase + r;
            int gj = k0 + c4;
            float4 mv = *(const float4*)&g_mult1[(size_t)gi * N_NODES + gj];
            float4 av = *(const float4*)&adj_v[(size_t)gi * N_NODES + gj];
            float m0 = (gi == gj + 0) ? 1.f : mv.x;
            float m1 = (gi == gj + 1) ? 1.f : mv.y;
            float m2 = (gi == gj + 2) ? 1.f : mv.z;
            float m3 = (gi == gj + 3) ? 1.f : mv.w;
            As[c4 + 0][r] = 0.5f * (m0 + 1.f) * av.x;
            As[c4 + 1][r] = 0.5f * (m1 + 1.f) * av.y;
            As[c4 + 2][r] = 0.5f * (m2 + 1.f) * av.z;
            As[c4 + 3][r] = 0.5f * (m3 + 1.f) * av.w;
        }
#pragma unroll
        for (int l = 0; l < 2; l++) {
            int t  = tid + l * 256;
            int r  = t >> 5;
            int c4 = (t & 31) * 4;
            *(float4*)&Bs[r][c4] =
                *(const float4*)&Hv[(size_t)(k0 + r) * IN_V + colbase + c4];
        }
        __syncthreads();

#pragma unroll
        for (int k = 0; k < 16; k++) {
            float a[8], b[8];
            *(float4*)&a[0] = *(float4*)&As[k][ty * 8];
            *(float4*)&a[4] = *(float4*)&As[k][ty * 8 + 4];
            *(float4*)&b[0] = *(float4*)&Bs[k][tx * 8];
            *(float4*)&b[4] = *(float4*)&Bs[k][tx * 8 + 4];
#pragma unroll
            for (int m = 0; m < 8; m++)
#pragma unroll
                for (int n = 0; n < 8; n++)
                    acc[m][n] = fmaf(a[m], b[n], acc[m][n]);
        }
        __syncthreads();
    }

#pragma unroll
    for (int m = 0; m < 8; m++) {
        int gi = rowbase + ty * 8 + m;
        float* yrow = g_Y + (size_t)gi * IN_V + colbase + tx * 8;
#pragma unroll
        for (int n = 0; n < 8; n += 4)
            *(float4*)&yrow[n] = make_float4(acc[m][n], acc[m][n + 1],
                                             acc[m][n + 2], acc[m][n + 3]);
    }
}

// ---------------------------------------------------------------------------
// Kernel 4: ret = Y @ W + bias
// ---------------------------------------------------------------------------
__global__ __launch_bounds__(256, 1)
void gemm3_kernel(const float* __restrict__ W,
                  const float* __restrict__ bias,
                  float* __restrict__ out) {
    __shared__ float As[16][128];
    __shared__ float Bs[16][128];

    const int tid = threadIdx.x;
    const int ty  = tid >> 4;
    const int tx  = tid & 15;
    const int rowbase = blockIdx.y * 128;
    const int colbase = blockIdx.x * 128;

    float acc[8][8];
#pragma unroll
    for (int m = 0; m < 8; m++)
#pragma unroll
        for (int n = 0; n < 8; n++) acc[m][n] = 0.f;

    for (int k0 = 0; k0 < IN_V; k0 += 16) {
#pragma unroll
        for (int l = 0; l < 2; l++) {
            int t  = tid + l * 256;
            int r  = t >> 2;
            int c4 = (t & 3) * 4;
            float4 v = *(const float4*)&g_Y[(size_t)(rowbase + r) * IN_V + k0 + c4];
            As[c4 + 0][r] = v.x;
            As[c4 + 1][r] = v.y;
            As[c4 + 2][r] = v.z;
            As[c4 + 3][r] = v.w;
        }
#pragma unroll
        for (int l = 0; l < 2; l++) {
            int t  = tid + l * 256;
            int r  = t >> 5;
            int c4 = (t & 31) * 4;
            *(float4*)&Bs[r][c4] =
                *(const float4*)&W[(size_t)(k0 + r) * OUT_V + colbase + c4];
        }
        __syncthreads();

#pragma unroll
        for (int k = 0; k < 16; k++) {
            float a[8], b[8];
            *(float4*)&a[0] = *(float4*)&As[k][ty * 8];
            *(float4*)&a[4] = *(float4*)&As[k][ty * 8 + 4];
            *(float4*)&b[0] = *(float4*)&Bs[k][tx * 8];
            *(float4*)&b[4] = *(float4*)&Bs[k][tx * 8 + 4];
#pragma unroll
            for (int m = 0; m < 8; m++)
#pragma unroll
                for (int n = 0; n < 8; n++)
                    acc[m][n] = fmaf(a[m], b[n], acc[m][n]);
        }
        __syncthreads();
    }

#pragma unroll
    for (int m = 0; m < 8; m++) {
        int gi = rowbase + ty * 8 + m;
        int gj = colbase + tx * 8;
        float* orow = out + (size_t)gi * OUT_V + gj;
#pragma unroll
        for (int n = 0; n < 8; n += 4) {
            float4 bv = *(const float4*)&bias[gj + n];
            *(float4*)&orow[n] = make_float4(acc[m][n] + bv.x, acc[m][n + 1] + bv.y,
                                             acc[m][n + 2] + bv.z, acc[m][n + 3] + bv.w);
        }
    }
}

// ---------------------------------------------------------------------------
extern "C" void kernel_launch(void* const* d_in, const int* in_sizes, int n_in,
                              void* d_out, int out_size) {
    const float* H_v   = (const float*)d_in[0];
    const float* H_e   = (const float*)d_in[1];
    // d_in[2] = adj_e : unused by the reference
    const float* adj_v = (const float*)d_in[3];
    const float* T     = (const float*)d_in[4];
    const float* W     = (const float*)d_in[5];
    const float* p     = (const float*)d_in[6];
    const float* bias  = (const float*)d_in[7];
    float* out = (float*)d_out;

    // 1. e = H_e @ p^T
    escale_kernel<<<E_EDGES / 8, 256>>>(H_e, p);

    // 1b. bf16 hi/lo split of G = T*diag(e) and T
    convert_kernel<<<(N_NODES * (E_EDGES / 4)) / 256, 256>>>(T);

    // 2. mult1 = G @ T^T  (mma.sync bf16 split)
    static bool attr_done = false;
    if (!attr_done) {
        cudaFuncSetAttribute(gemm1_mma, cudaFuncAttributeMaxDynamicSharedMemorySize,
                             GEMM1_SMEM);
        attr_done = true;
    }
    gemm1_mma<<<dim3(32, 32), 256, GEMM1_SMEM>>>();

    // 3. Y = (0.5*(M1'+1) .* adj_v) @ H_v
    {
        dim3 grid(IN_V / 128, N_NODES / 128);
        gemm2_kernel<<<grid, 256>>>(adj_v, H_v);
    }

    // 4. ret = Y @ W + bias
    {
        dim3 grid(OUT_V / 128, N_NODES / 128);
        gemm3_kernel<<<grid, 256>>>(W, bias, out);
    }

    // 5. second output: H_e passthrough
    int he_elems = in_sizes[1];
    cudaMemcpyAsync(out + ((size_t)out_size - he_elems), H_e,
                    (size_t)he_elems * sizeof(float),
                    cudaMemcpyDeviceToDevice, 0);
}

// round 6
// speedup vs baseline: 5.4582x; 1.8600x over previous
#include <cuda_runtime.h>
#include <cuda_bf16.h>
#include <cstdint>
#include <cstddef>

// ---------------------------------------------------------------------------
// GraphConvolution (base sm_103: no tcgen05; mma.sync HMMA path):
//   e     = H_e @ p^T
//   M1    = (T*diag(e)) @ T^T          symmetric -> lower-tri tiles + mirror
//   Bcomb = 0.5*(M1'+1) .* adj_v       fused into gemm1 epilogue, bf16 hi/lo
//   Y     = Bcomb @ H_v                mma.sync bf16-split
//   ret   = Y @ W + bias               fp32 SIMT
//   out   = concat(ret, H_e)
// ---------------------------------------------------------------------------

#define N_NODES 4096
#define E_EDGES 8192
#define IN_V    512
#define OUT_V   512
#define IN_E    128
#define KC      64
#define NCHUNK1 (E_EDGES / KC)    // 128
#define NCHUNK2 (N_NODES / KC)    // 64
#define NTILES  32                // 4096/128
#define NTRI    (NTILES * (NTILES + 1) / 2)   // 528

// Static device scratch
__device__ float g_escale[E_EDGES];
__device__ float g_Y[(size_t)N_NODES * IN_V];                 // 8 MB
__device__ __nv_bfloat16 g_Ghi[(size_t)N_NODES * E_EDGES];    // 64 MB each
__device__ __nv_bfloat16 g_Glo[(size_t)N_NODES * E_EDGES];
__device__ __nv_bfloat16 g_Thi[(size_t)N_NODES * E_EDGES];
__device__ __nv_bfloat16 g_Tlo[(size_t)N_NODES * E_EDGES];
__device__ __nv_bfloat16 g_Bhi[(size_t)N_NODES * N_NODES];    // 32 MB each
__device__ __nv_bfloat16 g_Blo[(size_t)N_NODES * N_NODES];
__device__ __nv_bfloat16 g_HvThi[(size_t)IN_V * N_NODES];     // 4 MB each
__device__ __nv_bfloat16 g_HvTlo[(size_t)IN_V * N_NODES];

// ------------------------------ helpers ------------------------------------
__device__ __forceinline__ uint32_t smem_u32(const void* p) {
    uint32_t a;
    asm("{ .reg .u64 t; cvta.to.shared.u64 t, %1; cvt.u32.u64 %0, t; }"
        : "=r"(a) : "l"(p));
    return a;
}
__device__ __forceinline__ uint32_t swz(uint32_t x) { return x ^ ((x >> 3) & 0x70u); }

__device__ __forceinline__ void ldsm_x4(uint32_t& a0, uint32_t& a1,
                                        uint32_t& a2, uint32_t& a3, uint32_t addr) {
    asm volatile("ldmatrix.sync.aligned.m8n8.x4.shared.b16 {%0,%1,%2,%3}, [%4];"
                 : "=r"(a0), "=r"(a1), "=r"(a2), "=r"(a3) : "r"(addr));
}
__device__ __forceinline__ void ldsm_x2(uint32_t& b0, uint32_t& b1, uint32_t addr) {
    asm volatile("ldmatrix.sync.aligned.m8n8.x2.shared.b16 {%0,%1}, [%2];"
                 : "=r"(b0), "=r"(b1) : "r"(addr));
}
__device__ __forceinline__ void mma_bf16(float* d, const uint32_t* a, const uint32_t* b) {
    asm volatile(
        "mma.sync.aligned.m16n8k16.row.col.f32.bf16.bf16.f32 "
        "{%0,%1,%2,%3}, {%4,%5,%6,%7}, {%8,%9}, {%0,%1,%2,%3};"
        : "+f"(d[0]), "+f"(d[1]), "+f"(d[2]), "+f"(d[3])
        : "r"(a[0]), "r"(a[1]), "r"(a[2]), "r"(a[3]), "r"(b[0]), "r"(b[1]));
}
__device__ __forceinline__ void bsplit(float v, __nv_bfloat16& h, __nv_bfloat16& l) {
    h = __float2bfloat16(v);
    l = __float2bfloat16(v - __bfloat162float(h));
}

// ---------------------------------------------------------------------------
// Kernel 1: e[r] = dot(H_e[r,:], p)
// ---------------------------------------------------------------------------
__global__ void escale_kernel(const float* __restrict__ He,
                              const float* __restrict__ p) {
    int warp = threadIdx.x >> 5;
    int lane = threadIdx.x & 31;
    int row  = blockIdx.x * 8 + warp;
    if (row >= E_EDGES) return;
    const float* hr = He + (size_t)row * IN_E;
    float s = 0.f;
#pragma unroll
    for (int i = 0; i < IN_E; i += 32)
        s += hr[i + lane] * p[i + lane];
#pragma unroll
    for (int off = 16; off > 0; off >>= 1)
        s += __shfl_down_sync(0xffffffffu, s, off);
    if (lane == 0) g_escale[row] = s;
}

// ---------------------------------------------------------------------------
// Kernel 1b: split T and G=T*diag(e) into bf16 hi/lo pairs
// ---------------------------------------------------------------------------
__global__ __launch_bounds__(256)
void convert_kernel(const float* __restrict__ T) {
    unsigned g   = blockIdx.x * 256u + threadIdx.x;
    unsigned row = g >> 11;
    unsigned k4  = (g & 2047u) * 4u;
    size_t base = (size_t)row * E_EDGES + k4;
    float4 t = *(const float4*)(T + base);
    float4 e = *(const float4*)(g_escale + k4);
    float gv[4] = {t.x * e.x, t.y * e.y, t.z * e.z, t.w * e.w};
    float tv[4] = {t.x, t.y, t.z, t.w};
    unsigned short ghi[4], glo[4], thi[4], tlo[4];
#pragma unroll
    for (int i = 0; i < 4; i++) {
        __nv_bfloat16 h, l;
        bsplit(gv[i], h, l);
        ghi[i] = __bfloat16_as_ushort(h); glo[i] = __bfloat16_as_ushort(l);
        bsplit(tv[i], h, l);
        thi[i] = __bfloat16_as_ushort(h); tlo[i] = __bfloat16_as_ushort(l);
    }
#define PACK2(a) make_uint2((unsigned)(a)[0] | ((unsigned)(a)[1] << 16), \
                            (unsigned)(a)[2] | ((unsigned)(a)[3] << 16))
    *(uint2*)(g_Ghi + base) = PACK2(ghi);
    *(uint2*)(g_Glo + base) = PACK2(glo);
    *(uint2*)(g_Thi + base) = PACK2(thi);
    *(uint2*)(g_Tlo + base) = PACK2(tlo);
#undef PACK2
}

// ---------------------------------------------------------------------------
// Kernel 1c: HvT hi/lo split, transposed: HvT[n][k] = Hv[k][n]
// ---------------------------------------------------------------------------
__global__ __launch_bounds__(256)
void convert_hvt_kernel(const float* __restrict__ Hv) {
    __shared__ float tile[32][33];
    int tx = threadIdx.x & 31;
    int ty = threadIdx.x >> 5;           // 0..7
    int n0 = blockIdx.x * 32;
    int k0 = blockIdx.y * 32;
#pragma unroll
    for (int i = ty; i < 32; i += 8)
        tile[i][tx] = Hv[(size_t)(k0 + i) * IN_V + n0 + tx];
    __syncthreads();
#pragma unroll
    for (int i = ty; i < 32; i += 8) {
        float v = tile[tx][i];           // k = k0+tx, n = n0+i
        __nv_bfloat16 h, l;
        bsplit(v, h, l);
        size_t idx = (size_t)(n0 + i) * N_NODES + k0 + tx;
        g_HvThi[idx] = h;
        g_HvTlo[idx] = l;
    }
}

// ---------------------------------------------------------------------------
// Kernel 2: lower-tri tiles of M1 = G @ T^T (bf16 split, mma.sync),
// fused epilogue: Bcomb = 0.5*(M1'+1).*adj_v -> bf16 hi/lo, + mirrored tile.
// ---------------------------------------------------------------------------
#define STAGE_BYTES 65536
#define GEMM_SMEM   (2 * STAGE_BYTES)

__global__ __launch_bounds__(256, 1)
void gemm1_mma(const float* __restrict__ adj_v) {
    extern __shared__ char smem[];
    uint32_t sb = smem_u32(smem);
    const int tid  = threadIdx.x;
    const int wid  = tid >> 5;
    const int lane = tid & 31;
    const int wr   = wid >> 2;
    const int wc   = wid & 3;

    // linear block id -> lower-tri (rowtile, coltile), coltile <= rowtile
    unsigned l = blockIdx.x;
    unsigned rt = (unsigned)((sqrtf(8.f * (float)l + 1.f) - 1.f) * 0.5f);
    while ((rt + 1u) * (rt + 2u) / 2u <= l) rt++;
    while (rt * (rt + 1u) / 2u > l) rt--;
    unsigned ct = l - rt * (rt + 1u) / 2u;
    const unsigned rowbase = rt * 128u;
    const unsigned colbase = ct * 128u;
    const bool diag = (rt == ct);

    float acc[4][4][4];
#pragma unroll
    for (int m = 0; m < 4; m++)
#pragma unroll
        for (int n = 0; n < 4; n++)
#pragma unroll
            for (int i = 0; i < 4; i++) acc[m][n][i] = 0.f;

    auto load_chunk = [&](int c, int s) {
        uint32_t sbase = sb + (uint32_t)s * STAGE_BYTES;
        unsigned kbase = (unsigned)c * KC;
#pragma unroll
        for (int i = 0; i < 16; i++) {
            const int arr = i >> 2;
            const int ci  = (i & 3) * 256 + tid;
            const int r   = ci >> 3;
            const int q   = ci & 7;
            const __nv_bfloat16* src;
            unsigned grow;
            if (arr == 0)      { src = g_Ghi; grow = rowbase + r; }
            else if (arr == 1) { src = g_Glo; grow = rowbase + r; }
            else if (arr == 2) { src = g_Thi; grow = colbase + r; }
            else               { src = g_Tlo; grow = colbase + r; }
            const void* gp = (const void*)(src + (size_t)grow * E_EDGES + kbase + q * 8);
            uint32_t dp = sbase + (uint32_t)arr * 16384u + swz((uint32_t)(r * 128 + q * 16));
            asm volatile("cp.async.cg.shared.global [%0], [%1], 16;" :: "r"(dp), "l"(gp));
        }
    };

    load_chunk(0, 0);
    asm volatile("cp.async.commit_group;" ::: "memory");

    for (int c = 0; c < NCHUNK1; c++) {
        int s = c & 1;
        if (c + 1 < NCHUNK1) load_chunk(c + 1, s ^ 1);
        asm volatile("cp.async.commit_group;" ::: "memory");
        asm volatile("cp.async.wait_group 1;" ::: "memory");
        __syncthreads();

        uint32_t stage = sb + (uint32_t)s * STAGE_BYTES;
        uint32_t aHiB = stage;
        uint32_t aLoB = stage + 16384u;
        uint32_t bHiB = stage + 32768u;
        uint32_t bLoB = stage + 49152u;

        const int la_row = lane & 15;
        const int la_kh  = lane >> 4;
        const int lb     = lane & 15;
        const int lb_row = lb & 7;
        const int lb_kh  = (lb >> 3) & 1;

#pragma unroll
        for (int ks = 0; ks < 4; ks++) {
            uint32_t ahi[4][4], alo[4][4], bhi[4][2], blo[4][2];
#pragma unroll
            for (int mt = 0; mt < 4; mt++) {
                uint32_t off = swz((uint32_t)((wr * 64 + mt * 16 + la_row) * 128
                                              + ks * 32 + la_kh * 16));
                ldsm_x4(ahi[mt][0], ahi[mt][1], ahi[mt][2], ahi[mt][3], aHiB + off);
                ldsm_x4(alo[mt][0], alo[mt][1], alo[mt][2], alo[mt][3], aLoB + off);
            }
#pragma unroll
            for (int nt = 0; nt < 4; nt++) {
                uint32_t off = swz((uint32_t)((wc * 32 + nt * 8 + lb_row) * 128
                                              + ks * 32 + lb_kh * 16));
                ldsm_x2(bhi[nt][0], bhi[nt][1], bHiB + off);
                ldsm_x2(blo[nt][0], blo[nt][1], bLoB + off);
            }
#pragma unroll
            for (int mt = 0; mt < 4; mt++)
#pragma unroll
                for (int nt = 0; nt < 4; nt++) {
                    mma_bf16(acc[mt][nt], ahi[mt], bhi[nt]);
                    mma_bf16(acc[mt][nt], ahi[mt], blo[nt]);
                    mma_bf16(acc[mt][nt], alo[mt], bhi[nt]);
                }
        }
        __syncthreads();
    }

    // Fused epilogue -> Bcomb bf16 hi/lo at (r,c), and mirrored (c,r).
#pragma unroll
    for (int mt = 0; mt < 4; mt++) {
        unsigned r0 = rowbase + wr * 64 + mt * 16 + (lane >> 2);
        unsigned r1 = r0 + 8;
#pragma unroll
        for (int nt = 0; nt < 4; nt++) {
            unsigned cc = colbase + wc * 32 + nt * 8 + 2 * (lane & 3);
            float2 a0 = *(const float2*)&adj_v[(size_t)r0 * N_NODES + cc];
            float2 a1 = *(const float2*)&adj_v[(size_t)r1 * N_NODES + cc];
            float b00 = (r0 == cc)     ? a0.x : 0.5f * (acc[mt][nt][0] + 1.f) * a0.x;
            float b01 = (r0 == cc + 1) ? a0.y : 0.5f * (acc[mt][nt][1] + 1.f) * a0.y;
            float b10 = (r1 == cc)     ? a1.x : 0.5f * (acc[mt][nt][2] + 1.f) * a1.x;
            float b11 = (r1 == cc + 1) ? a1.y : 0.5f * (acc[mt][nt][3] + 1.f) * a1.y;
            __nv_bfloat16 h00, l00, h01, l01, h10, l10, h11, l11;
            bsplit(b00, h00, l00); bsplit(b01, h01, l01);
            bsplit(b10, h10, l10); bsplit(b11, h11, l11);
            *(uint32_t*)&g_Bhi[(size_t)r0 * N_NODES + cc] =
                (uint32_t)__bfloat16_as_ushort(h00) | ((uint32_t)__bfloat16_as_ushort(h01) << 16);
            *(uint32_t*)&g_Blo[(size_t)r0 * N_NODES + cc] =
                (uint32_t)__bfloat16_as_ushort(l00) | ((uint32_t)__bfloat16_as_ushort(l01) << 16);
            *(uint32_t*)&g_Bhi[(size_t)r1 * N_NODES + cc] =
                (uint32_t)__bfloat16_as_ushort(h10) | ((uint32_t)__bfloat16_as_ushort(h11) << 16);
            *(uint32_t*)&g_Blo[(size_t)r1 * N_NODES + cc] =
                (uint32_t)__bfloat16_as_ushort(l10) | ((uint32_t)__bfloat16_as_ushort(l11) << 16);

            if (!diag) {
                // mirror: Bcomb[c][r] = 0.5*(M1[r][c]+1)*adj_v[c][r]
                float am00 = adj_v[(size_t)cc * N_NODES + r0];
                float am01 = adj_v[(size_t)(cc + 1) * N_NODES + r0];
                float am10 = adj_v[(size_t)cc * N_NODES + r1];
                float am11 = adj_v[(size_t)(cc + 1) * N_NODES + r1];
                float m00 = 0.5f * (acc[mt][nt][0] + 1.f) * am00;
                float m01 = 0.5f * (acc[mt][nt][1] + 1.f) * am01;
                float m10 = 0.5f * (acc[mt][nt][2] + 1.f) * am10;
                float m11 = 0.5f * (acc[mt][nt][3] + 1.f) * am11;
                __nv_bfloat16 h, l2;
                bsplit(m00, h, l2);
                g_Bhi[(size_t)cc * N_NODES + r0] = h;  g_Blo[(size_t)cc * N_NODES + r0] = l2;
                bsplit(m01, h, l2);
                g_Bhi[(size_t)(cc + 1) * N_NODES + r0] = h;  g_Blo[(size_t)(cc + 1) * N_NODES + r0] = l2;
                bsplit(m10, h, l2);
                g_Bhi[(size_t)cc * N_NODES + r1] = h;  g_Blo[(size_t)cc * N_NODES + r1] = l2;
                bsplit(m11, h, l2);
                g_Bhi[(size_t)(cc + 1) * N_NODES + r1] = h;  g_Blo[(size_t)(cc + 1) * N_NODES + r1] = l2;
            }
        }
    }
}

// ---------------------------------------------------------------------------
// Kernel 3: Y = Bcomb @ H_v via bf16-split mma.sync.  M=4096,N=512,K=4096.
// A = g_Bhi/g_Blo [4096][4096], B = g_HvThi/lo [512][4096] (both K-major).
// ---------------------------------------------------------------------------
__global__ __launch_bounds__(256, 1)
void gemm2_mma() {
    extern __shared__ char smem[];
    uint32_t sb = smem_u32(smem);
    const int tid  = threadIdx.x;
    const int wid  = tid >> 5;
    const int lane = tid & 31;
    const int wr   = wid >> 2;
    const int wc   = wid & 3;

    const unsigned rowbase = blockIdx.y * 128u;
    const unsigned colbase = blockIdx.x * 128u;

    float acc[4][4][4];
#pragma unroll
    for (int m = 0; m < 4; m++)
#pragma unroll
        for (int n = 0; n < 4; n++)
#pragma unroll
            for (int i = 0; i < 4; i++) acc[m][n][i] = 0.f;

    auto load_chunk = [&](int c, int s) {
        uint32_t sbase = sb + (uint32_t)s * STAGE_BYTES;
        unsigned kbase = (unsigned)c * KC;
#pragma unroll
        for (int i = 0; i < 16; i++) {
            const int arr = i >> 2;
            const int ci  = (i & 3) * 256 + tid;
            const int r   = ci >> 3;
            const int q   = ci & 7;
            const __nv_bfloat16* src;
            unsigned grow;
            if (arr == 0)      { src = g_Bhi;   grow = rowbase + r; }
            else if (arr == 1) { src = g_Blo;   grow = rowbase + r; }
            else if (arr == 2) { src = g_HvThi; grow = colbase + r; }
            else               { src = g_HvTlo; grow = colbase + r; }
            const void* gp = (const void*)(src + (size_t)grow * N_NODES + kbase + q * 8);
            uint32_t dp = sbase + (uint32_t)arr * 16384u + swz((uint32_t)(r * 128 + q * 16));
            asm volatile("cp.async.cg.shared.global [%0], [%1], 16;" :: "r"(dp), "l"(gp));
        }
    };

    load_chunk(0, 0);
    asm volatile("cp.async.commit_group;" ::: "memory");

    for (int c = 0; c < NCHUNK2; c++) {
        int s = c & 1;
        if (c + 1 < NCHUNK2) load_chunk(c + 1, s ^ 1);
        asm volatile("cp.async.commit_group;" ::: "memory");
        asm volatile("cp.async.wait_group 1;" ::: "memory");
        __syncthreads();

        uint32_t stage = sb + (uint32_t)s * STAGE_BYTES;
        uint32_t aHiB = stage;
        uint32_t aLoB = stage + 16384u;
        uint32_t bHiB = stage + 32768u;
        uint32_t bLoB = stage + 49152u;

        const int la_row = lane & 15;
        const int la_kh  = lane >> 4;
        const int lb     = lane & 15;
        const int lb_row = lb & 7;
        const int lb_kh  = (lb >> 3) & 1;

#pragma unroll
        for (int ks = 0; ks < 4; ks++) {
            uint32_t ahi[4][4], alo[4][4], bhi[4][2], blo[4][2];
#pragma unroll
            for (int mt = 0; mt < 4; mt++) {
                uint32_t off = swz((uint32_t)((wr * 64 + mt * 16 + la_row) * 128
                                              + ks * 32 + la_kh * 16));
                ldsm_x4(ahi[mt][0], ahi[mt][1], ahi[mt][2], ahi[mt][3], aHiB + off);
                ldsm_x4(alo[mt][0], alo[mt][1], alo[mt][2], alo[mt][3], aLoB + off);
            }
#pragma unroll
            for (int nt = 0; nt < 4; nt++) {
                uint32_t off = swz((uint32_t)((wc * 32 + nt * 8 + lb_row) * 128
                                              + ks * 32 + lb_kh * 16));
                ldsm_x2(bhi[nt][0], bhi[nt][1], bHiB + off);
                ldsm_x2(blo[nt][0], blo[nt][1], bLoB + off);
            }
#pragma unroll
            for (int mt = 0; mt < 4; mt++)
#pragma unroll
                for (int nt = 0; nt < 4; nt++) {
                    mma_bf16(acc[mt][nt], ahi[mt], bhi[nt]);
                    mma_bf16(acc[mt][nt], ahi[mt], blo[nt]);
                    mma_bf16(acc[mt][nt], alo[mt], bhi[nt]);
                }
        }
        __syncthreads();
    }

#pragma unroll
    for (int mt = 0; mt < 4; mt++) {
        unsigned r0 = rowbase + wr * 64 + mt * 16 + (lane >> 2);
#pragma unroll
        for (int nt = 0; nt < 4; nt++) {
            unsigned cc = colbase + wc * 32 + nt * 8 + 2 * (lane & 3);
            *(float2*)&g_Y[(size_t)r0 * IN_V + cc] =
                make_float2(acc[mt][nt][0], acc[mt][nt][1]);
            *(float2*)&g_Y[(size_t)(r0 + 8) * IN_V + cc] =
                make_float2(acc[mt][nt][2], acc[mt][nt][3]);
        }
    }
}

// ---------------------------------------------------------------------------
// Kernel 4: ret = Y @ W + bias  (fp32 SIMT, small)
// ---------------------------------------------------------------------------
__global__ __launch_bounds__(256, 1)
void gemm3_kernel(const float* __restrict__ W,
                  const float* __restrict__ bias,
                  float* __restrict__ out) {
    __shared__ float As[16][128];
    __shared__ float Bs[16][128];

    const int tid = threadIdx.x;
    const int ty  = tid >> 4;
    const int tx  = tid & 15;
    const int rowbase = blockIdx.y * 128;
    const int colbase = blockIdx.x * 128;

    float acc[8][8];
#pragma unroll
    for (int m = 0; m < 8; m++)
#pragma unroll
        for (int n = 0; n < 8; n++) acc[m][n] = 0.f;

    for (int k0 = 0; k0 < IN_V; k0 += 16) {
#pragma unroll
        for (int l = 0; l < 2; l++) {
            int t  = tid + l * 256;
            int r  = t >> 2;
            int c4 = (t & 3) * 4;
            float4 v = *(const float4*)&g_Y[(size_t)(rowbase + r) * IN_V + k0 + c4];
            As[c4 + 0][r] = v.x;
            As[c4 + 1][r] = v.y;
            As[c4 + 2][r] = v.z;
            As[c4 + 3][r] = v.w;
        }
#pragma unroll
        for (int l = 0; l < 2; l++) {
            int t  = tid + l * 256;
            int r  = t >> 5;
            int c4 = (t & 31) * 4;
            *(float4*)&Bs[r][c4] =
                *(const float4*)&W[(size_t)(k0 + r) * OUT_V + colbase + c4];
        }
        __syncthreads();

#pragma unroll
        for (int k = 0; k < 16; k++) {
            float a[8], b[8];
            *(float4*)&a[0] = *(float4*)&As[k][ty * 8];
            *(float4*)&a[4] = *(float4*)&As[k][ty * 8 + 4];
            *(float4*)&b[0] = *(float4*)&Bs[k][tx * 8];
            *(float4*)&b[4] = *(float4*)&Bs[k][tx * 8 + 4];
#pragma unroll
            for (int m = 0; m < 8; m++)
#pragma unroll
                for (int n = 0; n < 8; n++)
                    acc[m][n] = fmaf(a[m], b[n], acc[m][n]);
        }
        __syncthreads();
    }

#pragma unroll
    for (int m = 0; m < 8; m++) {
        int gi = rowbase + ty * 8 + m;
        int gj = colbase + tx * 8;
        float* orow = out + (size_t)gi * OUT_V + gj;
#pragma unroll
        for (int n = 0; n < 8; n += 4) {
            float4 bv = *(const float4*)&bias[gj + n];
            *(float4*)&orow[n] = make_float4(acc[m][n] + bv.x, acc[m][n + 1] + bv.y,
                                             acc[m][n + 2] + bv.z, acc[m][n + 3] + bv.w);
        }
    }
}

// ---------------------------------------------------------------------------
extern "C" void kernel_launch(void* const* d_in, const int* in_sizes, int n_in,
                              void* d_out, int out_size) {
    const float* H_v   = (const float*)d_in[0];
    const float* H_e   = (const float*)d_in[1];
    // d_in[2] = adj_e : unused by the reference
    const float* adj_v = (const float*)d_in[3];
    const float* T     = (const float*)d_in[4];
    const float* W     = (const float*)d_in[5];
    const float* p     = (const float*)d_in[6];
    const float* bias  = (const float*)d_in[7];
    float* out = (float*)d_out;

    static bool attr_done = false;
    if (!attr_done) {
        cudaFuncSetAttribute(gemm1_mma, cudaFuncAttributeMaxDynamicSharedMemorySize,
                             GEMM_SMEM);
        cudaFuncSetAttribute(gemm2_mma, cudaFuncAttributeMaxDynamicSharedMemorySize,
                             GEMM_SMEM);
        attr_done = true;
    }

    // 1. e = H_e @ p^T
    escale_kernel<<<E_EDGES / 8, 256>>>(H_e, p);

    // 1b. bf16 hi/lo split of G = T*diag(e) and T
    convert_kernel<<<(N_NODES * (E_EDGES / 4)) / 256, 256>>>(T);

    // 1c. HvT hi/lo (transposed split of H_v)
    convert_hvt_kernel<<<dim3(IN_V / 32, N_NODES / 32), 256>>>(H_v);

    // 2. lower-tri M1 tiles + fused Bcomb bf16 epilogue (incl. mirror)
    gemm1_mma<<<NTRI, 256, GEMM_SMEM>>>(adj_v);

    // 3. Y = Bcomb @ H_v  (bf16-split mma)
    gemm2_mma<<<dim3(IN_V / 128, N_NODES / 128), 256, GEMM_SMEM>>>();

    // 4. ret = Y @ W + bias
    gemm3_kernel<<<dim3(OUT_V / 128, N_NODES / 128), 256>>>(W, bias, out);

    // 5. second output: H_e passthrough
    int he_elems = in_sizes[1];
    cudaMemcpyAsync(out + ((size_t)out_size - he_elems), H_e,
                    (size_t)he_elems * sizeof(float),
                    cudaMemcpyDeviceToDevice, 0);
}

// round 7
// speedup vs baseline: 5.7041x; 1.0450x over previous
#include <cuda_runtime.h>
#include <cuda_bf16.h>
#include <cstdint>
#include <cstddef>

// ---------------------------------------------------------------------------
// GraphConvolution (base sm_103: mma.sync HMMA path, no tcgen05):
//   e     = H_e @ p^T
//   M1    = (T*diag(e)) @ T^T        symmetric -> lower-tri tiles + mirror
//   Bcomb = 0.5*(M1'+1) .* adj_v     fused into gemm1 epilogue, bf16 hi/lo
//   Y     = Bcomb @ H_v              bf16-split mma, epilogue emits Y hi/lo
//   ret   = Y @ W + bias             bf16-split mma
//   out   = concat(ret, H_e)
// All big GEMMs: 3-product bf16 hi/lo split (Ozaki), fp32 accumulate.
// ---------------------------------------------------------------------------

#define N_NODES 4096
#define E_EDGES 8192
#define IN_V    512
#define OUT_V   512
#define IN_E    128
#define KC      64
#define NCHUNK1 (E_EDGES / KC)    // 128
#define NCHUNK2 (N_NODES / KC)    // 64
#define NCHUNK3 (IN_V / KC)       // 8
#define NTILES  32
#define NTRI    (NTILES * (NTILES + 1) / 2)   // 528

#define STAGE_BYTES 65536
#define NSTAGE      3
#define GEMM_SMEM   (NSTAGE * STAGE_BYTES)

// Static device scratch
__device__ float g_escale[E_EDGES];
__device__ __nv_bfloat16 g_Ghi[(size_t)N_NODES * E_EDGES];    // 64 MB each
__device__ __nv_bfloat16 g_Glo[(size_t)N_NODES * E_EDGES];
__device__ __nv_bfloat16 g_Thi[(size_t)N_NODES * E_EDGES];
__device__ __nv_bfloat16 g_Tlo[(size_t)N_NODES * E_EDGES];
__device__ __nv_bfloat16 g_Bhi[(size_t)N_NODES * N_NODES];    // 32 MB each
__device__ __nv_bfloat16 g_Blo[(size_t)N_NODES * N_NODES];
__device__ __nv_bfloat16 g_HvThi[(size_t)IN_V * N_NODES];     // 4 MB each
__device__ __nv_bfloat16 g_HvTlo[(size_t)IN_V * N_NODES];
__device__ __nv_bfloat16 g_Yhi[(size_t)N_NODES * IN_V];       // 4 MB each
__device__ __nv_bfloat16 g_Ylo[(size_t)N_NODES * IN_V];
__device__ __nv_bfloat16 g_WThi[(size_t)OUT_V * IN_V];        // 0.5 MB each
__device__ __nv_bfloat16 g_WTlo[(size_t)OUT_V * IN_V];

// ------------------------------ helpers ------------------------------------
__device__ __forceinline__ uint32_t smem_u32(const void* p) {
    uint32_t a;
    asm("{ .reg .u64 t; cvta.to.shared.u64 t, %1; cvt.u32.u64 %0, t; }"
        : "=r"(a) : "l"(p));
    return a;
}
__device__ __forceinline__ uint32_t swz(uint32_t x) { return x ^ ((x >> 3) & 0x70u); }

__device__ __forceinline__ void ldsm_x4(uint32_t& a0, uint32_t& a1,
                                        uint32_t& a2, uint32_t& a3, uint32_t addr) {
    asm volatile("ldmatrix.sync.aligned.m8n8.x4.shared.b16 {%0,%1,%2,%3}, [%4];"
                 : "=r"(a0), "=r"(a1), "=r"(a2), "=r"(a3) : "r"(addr));
}
__device__ __forceinline__ void mma_bf16(float* d, const uint32_t* a, const uint32_t* b) {
    asm volatile(
        "mma.sync.aligned.m16n8k16.row.col.f32.bf16.bf16.f32 "
        "{%0,%1,%2,%3}, {%4,%5,%6,%7}, {%8,%9}, {%0,%1,%2,%3};"
        : "+f"(d[0]), "+f"(d[1]), "+f"(d[2]), "+f"(d[3])
        : "r"(a[0]), "r"(a[1]), "r"(a[2]), "r"(a[3]), "r"(b[0]), "r"(b[1]));
}
__device__ __forceinline__ void bsplit(float v, __nv_bfloat16& h, __nv_bfloat16& l) {
    h = __float2bfloat16(v);
    l = __float2bfloat16(v - __bfloat162float(h));
}
__device__ __forceinline__ void cpa16(uint32_t dst, const void* src) {
    asm volatile("cp.async.cg.shared.global [%0], [%1], 16;" :: "r"(dst), "l"(src));
}
#define CP_COMMIT() asm volatile("cp.async.commit_group;" ::: "memory")
#define CP_WAIT1()  asm volatile("cp.async.wait_group 1;" ::: "memory")

// ---------------------------------------------------------------------------
// Kernel 1: e[r] = dot(H_e[r,:], p)
// ---------------------------------------------------------------------------
__global__ void escale_kernel(const float* __restrict__ He,
                              const float* __restrict__ p) {
    int warp = threadIdx.x >> 5;
    int lane = threadIdx.x & 31;
    int row  = blockIdx.x * 8 + warp;
    if (row >= E_EDGES) return;
    const float* hr = He + (size_t)row * IN_E;
    float s = 0.f;
#pragma unroll
    for (int i = 0; i < IN_E; i += 32)
        s += hr[i + lane] * p[i + lane];
#pragma unroll
    for (int off = 16; off > 0; off >>= 1)
        s += __shfl_down_sync(0xffffffffu, s, off);
    if (lane == 0) g_escale[row] = s;
}

// ---------------------------------------------------------------------------
// Kernel 1b: split T and G=T*diag(e) into bf16 hi/lo pairs
// ---------------------------------------------------------------------------
__global__ __launch_bounds__(256)
void convert_kernel(const float* __restrict__ T) {
    unsigned g   = blockIdx.x * 256u + threadIdx.x;
    unsigned row = g >> 11;
    unsigned k4  = (g & 2047u) * 4u;
    size_t base = (size_t)row * E_EDGES + k4;
    float4 t = *(const float4*)(T + base);
    float4 e = *(const float4*)(g_escale + k4);
    float gv[4] = {t.x * e.x, t.y * e.y, t.z * e.z, t.w * e.w};
    float tv[4] = {t.x, t.y, t.z, t.w};
    unsigned short ghi[4], glo[4], thi[4], tlo[4];
#pragma unroll
    for (int i = 0; i < 4; i++) {
        __nv_bfloat16 h, l;
        bsplit(gv[i], h, l);
        ghi[i] = __bfloat16_as_ushort(h); glo[i] = __bfloat16_as_ushort(l);
        bsplit(tv[i], h, l);
        thi[i] = __bfloat16_as_ushort(h); tlo[i] = __bfloat16_as_ushort(l);
    }
#define PACK2(a) make_uint2((unsigned)(a)[0] | ((unsigned)(a)[1] << 16), \
                            (unsigned)(a)[2] | ((unsigned)(a)[3] << 16))
    *(uint2*)(g_Ghi + base) = PACK2(ghi);
    *(uint2*)(g_Glo + base) = PACK2(glo);
    *(uint2*)(g_Thi + base) = PACK2(thi);
    *(uint2*)(g_Tlo + base) = PACK2(tlo);
#undef PACK2
}

// ---------------------------------------------------------------------------
// Kernel 1c: transposed hi/lo splits of H_v (-> [IN_V][N]) and W (-> [OUT_V][IN_V])
// ---------------------------------------------------------------------------
__global__ __launch_bounds__(256)
void convert_hvt_kernel(const float* __restrict__ Hv) {
    __shared__ float tile[32][33];
    int tx = threadIdx.x & 31;
    int ty = threadIdx.x >> 5;
    int n0 = blockIdx.x * 32;
    int k0 = blockIdx.y * 32;
#pragma unroll
    for (int i = ty; i < 32; i += 8)
        tile[i][tx] = Hv[(size_t)(k0 + i) * IN_V + n0 + tx];
    __syncthreads();
#pragma unroll
    for (int i = ty; i < 32; i += 8) {
        float v = tile[tx][i];
        __nv_bfloat16 h, l;
        bsplit(v, h, l);
        size_t idx = (size_t)(n0 + i) * N_NODES + k0 + tx;
        g_HvThi[idx] = h;
        g_HvTlo[idx] = l;
    }
}

__global__ __launch_bounds__(256)
void convert_wt_kernel(const float* __restrict__ W) {
    __shared__ float tile[32][33];
    int tx = threadIdx.x & 31;
    int ty = threadIdx.x >> 5;
    int n0 = blockIdx.x * 32;
    int k0 = blockIdx.y * 32;
#pragma unroll
    for (int i = ty; i < 32; i += 8)
        tile[i][tx] = W[(size_t)(k0 + i) * OUT_V + n0 + tx];
    __syncthreads();
#pragma unroll
    for (int i = ty; i < 32; i += 8) {
        float v = tile[tx][i];
        __nv_bfloat16 h, l;
        bsplit(v, h, l);
        size_t idx = (size_t)(n0 + i) * IN_V + k0 + tx;
        g_WThi[idx] = h;
        g_WTlo[idx] = l;
    }
}

// ---------------------------------------------------------------------------
// Shared MMA mainloop macro pieces (128x128 tile, 8 warps, 3-product split)
//   fragment loads: A via ldsm x4 per 16-row tile; B via ldsm x4 per n-tile PAIR.
// ---------------------------------------------------------------------------
struct FragCtx {
    int wr, wc, lane;
};

__device__ __forceinline__ void mma_chunk(uint32_t stage, const FragCtx& f,
                                          float acc[4][4][4]) {
    uint32_t aHiB = stage;
    uint32_t aLoB = stage + 16384u;
    uint32_t bHiB = stage + 32768u;
    uint32_t bLoB = stage + 49152u;
    const int lane = f.lane;
    const int la_row = lane & 15;
    const int la_kh  = lane >> 4;
    // B x4 pairing: lanes 0-7 -> (nt even, kh0); 8-15 -> (nt even, kh1);
    //               16-23 -> (nt odd, kh0); 24-31 -> (nt odd, kh1)
    const int gB   = lane >> 3;
    const int rB   = lane & 7;
    const int ntO  = gB >> 1;        // 0: even nt of pair, 1: odd nt
    const int khB  = gB & 1;

#pragma unroll
    for (int ks = 0; ks < 4; ks++) {
        uint32_t ahi[4][4], alo[4][4], bhi[4][2], blo[4][2];
#pragma unroll
        for (int mt = 0; mt < 4; mt++) {
            uint32_t off = swz((uint32_t)((f.wr * 64 + mt * 16 + la_row) * 128
                                          + ks * 32 + la_kh * 16));
            ldsm_x4(ahi[mt][0], ahi[mt][1], ahi[mt][2], ahi[mt][3], aHiB + off);
            ldsm_x4(alo[mt][0], alo[mt][1], alo[mt][2], alo[mt][3], aLoB + off);
        }
#pragma unroll
        for (int p = 0; p < 2; p++) {     // n-tile pairs (0,1) and (2,3)
            uint32_t off = swz((uint32_t)((f.wc * 32 + (p * 2 + ntO) * 8 + rB) * 128
                                          + ks * 32 + khB * 16));
            ldsm_x4(bhi[p * 2][0], bhi[p * 2][1], bhi[p * 2 + 1][0], bhi[p * 2 + 1][1],
                    bHiB + off);
            ldsm_x4(blo[p * 2][0], blo[p * 2][1], blo[p * 2 + 1][0], blo[p * 2 + 1][1],
                    bLoB + off);
        }
#pragma unroll
        for (int mt = 0; mt < 4; mt++)
#pragma unroll
            for (int nt = 0; nt < 4; nt++) {
                mma_bf16(acc[mt][nt], ahi[mt], bhi[nt]);
                mma_bf16(acc[mt][nt], ahi[mt], blo[nt]);
                mma_bf16(acc[mt][nt], alo[mt], bhi[nt]);
            }
    }
}

// ---------------------------------------------------------------------------
// Kernel 2: lower-tri tiles of M1 = G @ T^T, fused Bcomb bf16 epilogue+mirror
// ---------------------------------------------------------------------------
__global__ __launch_bounds__(256, 1)
void gemm1_mma(const float* __restrict__ adj_v) {
    extern __shared__ char smem[];
    uint32_t sb = smem_u32(smem);
    const int tid  = threadIdx.x;
    const int wid  = tid >> 5;
    const int lane = tid & 31;
    FragCtx f{wid >> 2, wid & 3, lane};

    unsigned l = blockIdx.x;
    unsigned rt = (unsigned)((sqrtf(8.f * (float)l + 1.f) - 1.f) * 0.5f);
    while ((rt + 1u) * (rt + 2u) / 2u <= l) rt++;
    while (rt * (rt + 1u) / 2u > l) rt--;
    unsigned ct = l - rt * (rt + 1u) / 2u;
    const unsigned rowbase = rt * 128u;
    const unsigned colbase = ct * 128u;
    const bool diag = (rt == ct);

    float acc[4][4][4];
#pragma unroll
    for (int m = 0; m < 4; m++)
#pragma unroll
        for (int n = 0; n < 4; n++)
#pragma unroll
            for (int i = 0; i < 4; i++) acc[m][n][i] = 0.f;

    auto load_chunk = [&](int c, int s) {
        uint32_t sbase = sb + (uint32_t)s * STAGE_BYTES;
        unsigned kbase = (unsigned)c * KC;
#pragma unroll
        for (int i = 0; i < 16; i++) {
            const int arr = i >> 2;
            const int ci  = (i & 3) * 256 + tid;
            const int r   = ci >> 3;
            const int q   = ci & 7;
            const __nv_bfloat16* src;
            unsigned grow;
            if (arr == 0)      { src = g_Ghi; grow = rowbase + r; }
            else if (arr == 1) { src = g_Glo; grow = rowbase + r; }
            else if (arr == 2) { src = g_Thi; grow = colbase + r; }
            else               { src = g_Tlo; grow = colbase + r; }
            cpa16(sbase + (uint32_t)arr * 16384u + swz((uint32_t)(r * 128 + q * 16)),
                  (const void*)(src + (size_t)grow * E_EDGES + kbase + q * 8));
        }
    };

    load_chunk(0, 0); CP_COMMIT();
    load_chunk(1, 1); CP_COMMIT();

    for (int c = 0; c < NCHUNK1; c++) {
        CP_WAIT1();
        __syncthreads();
        if (c + 2 < NCHUNK1) load_chunk(c + 2, (c + 2) % NSTAGE);
        CP_COMMIT();
        mma_chunk(sb + (uint32_t)(c % NSTAGE) * STAGE_BYTES, f, acc);
    }

    // Fused epilogue -> Bcomb bf16 hi/lo at (r,c) and mirror (c,r).
#pragma unroll
    for (int mt = 0; mt < 4; mt++) {
        unsigned r0 = rowbase + f.wr * 64 + mt * 16 + (lane >> 2);
        unsigned r1 = r0 + 8;
#pragma unroll
        for (int nt = 0; nt < 4; nt++) {
            unsigned cc = colbase + f.wc * 32 + nt * 8 + 2 * (lane & 3);
            float2 a0 = *(const float2*)&adj_v[(size_t)r0 * N_NODES + cc];
            float2 a1 = *(const float2*)&adj_v[(size_t)r1 * N_NODES + cc];
            float b00 = (r0 == cc)     ? a0.x : 0.5f * (acc[mt][nt][0] + 1.f) * a0.x;
            float b01 = (r0 == cc + 1) ? a0.y : 0.5f * (acc[mt][nt][1] + 1.f) * a0.y;
            float b10 = (r1 == cc)     ? a1.x : 0.5f * (acc[mt][nt][2] + 1.f) * a1.x;
            float b11 = (r1 == cc + 1) ? a1.y : 0.5f * (acc[mt][nt][3] + 1.f) * a1.y;
            __nv_bfloat16 h00, l00, h01, l01, h10, l10, h11, l11;
            bsplit(b00, h00, l00); bsplit(b01, h01, l01);
            bsplit(b10, h10, l10); bsplit(b11, h11, l11);
            *(uint32_t*)&g_Bhi[(size_t)r0 * N_NODES + cc] =
                (uint32_t)__bfloat16_as_ushort(h00) | ((uint32_t)__bfloat16_as_ushort(h01) << 16);
            *(uint32_t*)&g_Blo[(size_t)r0 * N_NODES + cc] =
                (uint32_t)__bfloat16_as_ushort(l00) | ((uint32_t)__bfloat16_as_ushort(l01) << 16);
            *(uint32_t*)&g_Bhi[(size_t)r1 * N_NODES + cc] =
                (uint32_t)__bfloat16_as_ushort(h10) | ((uint32_t)__bfloat16_as_ushort(h11) << 16);
            *(uint32_t*)&g_Blo[(size_t)r1 * N_NODES + cc] =
                (uint32_t)__bfloat16_as_ushort(l10) | ((uint32_t)__bfloat16_as_ushort(l11) << 16);

            if (!diag) {
                float am00 = adj_v[(size_t)cc * N_NODES + r0];
                float am01 = adj_v[(size_t)(cc + 1) * N_NODES + r0];
                float am10 = adj_v[(size_t)cc * N_NODES + r1];
                float am11 = adj_v[(size_t)(cc + 1) * N_NODES + r1];
                float m00 = 0.5f * (acc[mt][nt][0] + 1.f) * am00;
                float m01 = 0.5f * (acc[mt][nt][1] + 1.f) * am01;
                float m10 = 0.5f * (acc[mt][nt][2] + 1.f) * am10;
                float m11 = 0.5f * (acc[mt][nt][3] + 1.f) * am11;
                __nv_bfloat16 h, l2;
                bsplit(m00, h, l2);
                g_Bhi[(size_t)cc * N_NODES + r0] = h;  g_Blo[(size_t)cc * N_NODES + r0] = l2;
                bsplit(m01, h, l2);
                g_Bhi[(size_t)(cc + 1) * N_NODES + r0] = h;  g_Blo[(size_t)(cc + 1) * N_NODES + r0] = l2;
                bsplit(m10, h, l2);
                g_Bhi[(size_t)cc * N_NODES + r1] = h;  g_Blo[(size_t)cc * N_NODES + r1] = l2;
                bsplit(m11, h, l2);
                g_Bhi[(size_t)(cc + 1) * N_NODES + r1] = h;  g_Blo[(size_t)(cc + 1) * N_NODES + r1] = l2;
            }
        }
    }
}

// ---------------------------------------------------------------------------
// Kernel 3: Y = Bcomb @ H_v (bf16-split), epilogue emits Y as bf16 hi/lo
// ---------------------------------------------------------------------------
__global__ __launch_bounds__(256, 1)
void gemm2_mma() {
    extern __shared__ char smem[];
    uint32_t sb = smem_u32(smem);
    const int tid  = threadIdx.x;
    const int wid  = tid >> 5;
    const int lane = tid & 31;
    FragCtx f{wid >> 2, wid & 3, lane};

    const unsigned rowbase = blockIdx.y * 128u;
    const unsigned colbase = blockIdx.x * 128u;

    float acc[4][4][4];
#pragma unroll
    for (int m = 0; m < 4; m++)
#pragma unroll
        for (int n = 0; n < 4; n++)
#pragma unroll
            for (int i = 0; i < 4; i++) acc[m][n][i] = 0.f;

    auto load_chunk = [&](int c, int s) {
        uint32_t sbase = sb + (uint32_t)s * STAGE_BYTES;
        unsigned kbase = (unsigned)c * KC;
#pragma unroll
        for (int i = 0; i < 16; i++) {
            const int arr = i >> 2;
            const int ci  = (i & 3) * 256 + tid;
            const int r   = ci >> 3;
            const int q   = ci & 7;
            const __nv_bfloat16* src;
            unsigned grow;
            if (arr == 0)      { src = g_Bhi;   grow = rowbase + r; }
            else if (arr == 1) { src = g_Blo;   grow = rowbase + r; }
            else if (arr == 2) { src = g_HvThi; grow = colbase + r; }
            else               { src = g_HvTlo; grow = colbase + r; }
            cpa16(sbase + (uint32_t)arr * 16384u + swz((uint32_t)(r * 128 + q * 16)),
                  (const void*)(src + (size_t)grow * N_NODES + kbase + q * 8));
        }
    };

    load_chunk(0, 0); CP_COMMIT();
    load_chunk(1, 1); CP_COMMIT();

    for (int c = 0; c < NCHUNK2; c++) {
        CP_WAIT1();
        __syncthreads();
        if (c + 2 < NCHUNK2) load_chunk(c + 2, (c + 2) % NSTAGE);
        CP_COMMIT();
        mma_chunk(sb + (uint32_t)(c % NSTAGE) * STAGE_BYTES, f, acc);
    }

#pragma unroll
    for (int mt = 0; mt < 4; mt++) {
        unsigned r0 = rowbase + f.wr * 64 + mt * 16 + (lane >> 2);
#pragma unroll
        for (int nt = 0; nt < 4; nt++) {
            unsigned cc = colbase + f.wc * 32 + nt * 8 + 2 * (lane & 3);
            __nv_bfloat16 h0, l0, h1, l1;
            bsplit(acc[mt][nt][0], h0, l0); bsplit(acc[mt][nt][1], h1, l1);
            *(uint32_t*)&g_Yhi[(size_t)r0 * IN_V + cc] =
                (uint32_t)__bfloat16_as_ushort(h0) | ((uint32_t)__bfloat16_as_ushort(h1) << 16);
            *(uint32_t*)&g_Ylo[(size_t)r0 * IN_V + cc] =
                (uint32_t)__bfloat16_as_ushort(l0) | ((uint32_t)__bfloat16_as_ushort(l1) << 16);
            bsplit(acc[mt][nt][2], h0, l0); bsplit(acc[mt][nt][3], h1, l1);
            *(uint32_t*)&g_Yhi[(size_t)(r0 + 8) * IN_V + cc] =
                (uint32_t)__bfloat16_as_ushort(h0) | ((uint32_t)__bfloat16_as_ushort(h1) << 16);
            *(uint32_t*)&g_Ylo[(size_t)(r0 + 8) * IN_V + cc] =
                (uint32_t)__bfloat16_as_ushort(l0) | ((uint32_t)__bfloat16_as_ushort(l1) << 16);
        }
    }
}

// ---------------------------------------------------------------------------
// Kernel 4: ret = Y @ W + bias (bf16-split mma), K = IN_V = 512
// ---------------------------------------------------------------------------
__global__ __launch_bounds__(256, 1)
void gemm3_mma(const float* __restrict__ bias, float* __restrict__ out) {
    extern __shared__ char smem[];
    uint32_t sb = smem_u32(smem);
    const int tid  = threadIdx.x;
    const int wid  = tid >> 5;
    const int lane = tid & 31;
    FragCtx f{wid >> 2, wid & 3, lane};

    const unsigned rowbase = blockIdx.y * 128u;
    const unsigned colbase = blockIdx.x * 128u;

    float acc[4][4][4];
#pragma unroll
    for (int m = 0; m < 4; m++)
#pragma unroll
        for (int n = 0; n < 4; n++)
#pragma unroll
            for (int i = 0; i < 4; i++) acc[m][n][i] = 0.f;

    auto load_chunk = [&](int c, int s) {
        uint32_t sbase = sb + (uint32_t)s * STAGE_BYTES;
        unsigned kbase = (unsigned)c * KC;
#pragma unroll
        for (int i = 0; i < 16; i++) {
            const int arr = i >> 2;
            const int ci  = (i & 3) * 256 + tid;
            const int r   = ci >> 3;
            const int q   = ci & 7;
            const __nv_bfloat16* src;
            unsigned grow;
            if (arr == 0)      { src = g_Yhi;  grow = rowbase + r; }
            else if (arr == 1) { src = g_Ylo;  grow = rowbase + r; }
            else if (arr == 2) { src = g_WThi; grow = colbase + r; }
            else               { src = g_WTlo; grow = colbase + r; }
            cpa16(sbase + (uint32_t)arr * 16384u + swz((uint32_t)(r * 128 + q * 16)),
                  (const void*)(src + (size_t)grow * IN_V + kbase + q * 8));
        }
    };

    load_chunk(0, 0); CP_COMMIT();
    load_chunk(1, 1); CP_COMMIT();

    for (int c = 0; c < NCHUNK3; c++) {
        CP_WAIT1();
        __syncthreads();
        if (c + 2 < NCHUNK3) load_chunk(c + 2, (c + 2) % NSTAGE);
        CP_COMMIT();
        mma_chunk(sb + (uint32_t)(c % NSTAGE) * STAGE_BYTES, f, acc);
    }

#pragma unroll
    for (int mt = 0; mt < 4; mt++) {
        unsigned r0 = rowbase + f.wr * 64 + mt * 16 + (lane >> 2);
#pragma unroll
        for (int nt = 0; nt < 4; nt++) {
            unsigned cc = colbase + f.wc * 32 + nt * 8 + 2 * (lane & 3);
            float2 bv = *(const float2*)&bias[cc];
            *(float2*)&out[(size_t)r0 * OUT_V + cc] =
                make_float2(acc[mt][nt][0] + bv.x, acc[mt][nt][1] + bv.y);
            *(float2*)&out[(size_t)(r0 + 8) * OUT_V + cc] =
                make_float2(acc[mt][nt][2] + bv.x, acc[mt][nt][3] + bv.y);
        }
    }
}

// ---------------------------------------------------------------------------
extern "C" void kernel_launch(void* const* d_in, const int* in_sizes, int n_in,
                              void* d_out, int out_size) {
    const float* H_v   = (const float*)d_in[0];
    const float* H_e   = (const float*)d_in[1];
    // d_in[2] = adj_e : unused by the reference
    const float* adj_v = (const float*)d_in[3];
    const float* T     = (const float*)d_in[4];
    const float* W     = (const float*)d_in[5];
    const float* p     = (const float*)d_in[6];
    const float* bias  = (const float*)d_in[7];
    float* out = (float*)d_out;

    static bool attr_done = false;
    if (!attr_done) {
        cudaFuncSetAttribute(gemm1_mma, cudaFuncAttributeMaxDynamicSharedMemorySize, GEMM_SMEM);
        cudaFuncSetAttribute(gemm2_mma, cudaFuncAttributeMaxDynamicSharedMemorySize, GEMM_SMEM);
        cudaFuncSetAttribute(gemm3_mma, cudaFuncAttributeMaxDynamicSharedMemorySize, GEMM_SMEM);
        attr_done = true;
    }

    // 1. e = H_e @ p^T
    escale_kernel<<<E_EDGES / 8, 256>>>(H_e, p);

    // 1b. bf16 hi/lo split of G = T*diag(e) and T
    convert_kernel<<<(N_NODES * (E_EDGES / 4)) / 256, 256>>>(T);

    // 1c. transposed splits of H_v and W
    convert_hvt_kernel<<<dim3(IN_V / 32, N_NODES / 32), 256>>>(H_v);
    convert_wt_kernel<<<dim3(OUT_V / 32, IN_V / 32), 256>>>(W);

    // 2. lower-tri M1 tiles + fused Bcomb bf16 epilogue (incl. mirror)
    gemm1_mma<<<NTRI, 256, GEMM_SMEM>>>(adj_v);

    // 3. Y = Bcomb @ H_v  -> bf16 hi/lo
    gemm2_mma<<<dim3(IN_V / 128, N_NODES / 128), 256, GEMM_SMEM>>>();

    // 4. ret = Y @ W + bias
    gemm3_mma<<<dim3(OUT_V / 128, N_NODES / 128), 256, GEMM_SMEM>>>(bias, out);

    // 5. second output: H_e passthrough
    int he_elems = in_sizes[1];
    cudaMemcpyAsync(out + ((size_t)out_size - he_elems), H_e,
                    (size_t)he_elems * sizeof(float),
                    cudaMemcpyDeviceToDevice, 0);
}